// round 11
// baseline (speedup 1.0000x reference)
#include <cuda_runtime.h>
#include <cuda_bf16.h>

namespace {

constexpr int IMW = 1024;
constexpr int IMH = 1024;
constexpr int PY  = 8;        // output rows per thread (processed in vertical pairs)
constexpr int YB  = 4;        // blockDim.y

// alu-pipe comparator (FMNMX).
__device__ __forceinline__ void s2(float &a, float &b) {
    float t = fminf(a, b);
    b = fmaxf(a, b);
    a = t;
}

// fma-pipe comparator: min=(a+b-|a-b|)/2, max=(a+b+|a-b|)/2.
// 5 FADD/FMUL/FFMA ops; |.| is a free operand modifier. min'<=max' always
// (h>=0, rounding monotone). Error <= ~2 ulp absolute of max(|a|,|b|):
// equivalent to an exact comparator on data perturbed by ~1e-7 — harmless
// vs the 1e-3 threshold (aggregate rel err ~1e-7).
__device__ __forceinline__ void s2f(float &a, float &b) {
    const float d = a - b;
    const float s = a + b;
    const float h = fabsf(d) * 0.5f;
    a = __fmaf_rn(s, 0.5f, -h);
    b = __fmaf_rn(s, 0.5f,  h);
}

// 9-comparator sort5 (alu pipe).
__device__ __forceinline__ void sort5(float v[5]) {
    s2(v[0], v[1]); s2(v[2], v[3]); s2(v[0], v[2]); s2(v[1], v[3]); s2(v[1], v[2]);
    s2(v[3], v[4]); s2(v[2], v[3]); s2(v[1], v[2]); s2(v[0], v[1]);
}

// 5-comparator sort4 on the FMA pipe (inputs by value, outputs sorted).
__device__ __forceinline__ void sort4f(float a, float b, float c, float d,
                                       float &o0, float &o1, float &o2, float &o3) {
    s2f(a, b); s2f(c, d); s2f(a, c); s2f(b, d); s2f(b, c);
    o0 = a; o1 = b; o2 = c; o3 = d;
}

__device__ __forceinline__ float med3f(float a, float b, float c) {
    return fmaxf(fminf(a, b), fminf(fmaxf(a, b), c));
}

template <bool SAFE>
__device__ __forceinline__ void load_row(const float* __restrict__ img, int x, int yy,
                                         float v[5],
                                         bool okm2, bool okm1, bool okp1, bool okp2) {
    if (SAFE || (unsigned)yy < (unsigned)IMH) {
        const float* p = img + yy * IMW + x;
        v[0] = (SAFE || okm2) ? __ldg(p - 2) : 0.0f;
        v[1] = (SAFE || okm1) ? __ldg(p - 1) : 0.0f;
        v[2] = __ldg(p);
        v[3] = (SAFE || okp1) ? __ldg(p + 1) : 0.0f;
        v[4] = (SAFE || okp2) ? __ldg(p + 2) : 0.0f;
    } else {
        v[0] = v[1] = v[2] = v[3] = v[4] = 0.0f;
    }
}

template <bool SAFE>
__device__ __forceinline__ void process_strip(const float* __restrict__ img,
                                              float* __restrict__ outp,
                                              int x, int y0) {
    const bool okm2 = SAFE || (x >= 2);
    const bool okm1 = SAFE || (x >= 1);
    const bool okp1 = SAFE || (x <= IMW - 2);
    const bool okp2 = SAFE || (x <= IMW - 3);

    // Sorted horizontal 5-windows. For the pair (y, y+1):
    // r0 = y-2 (private to pixel A), r1..r4 = y-1..y+2 (common), r5 = y+3 (private B).
    float r0[5], r1[5], r2[5], r3[5], r4[5], r5[5];
    load_row<SAFE>(img, x, y0 - 2, r0, okm2, okm1, okp1, okp2); sort5(r0);
    load_row<SAFE>(img, x, y0 - 1, r1, okm2, okm1, okp1, okp2); sort5(r1);
    load_row<SAFE>(img, x, y0 + 0, r2, okm2, okm1, okp1, okp2); sort5(r2);
    load_row<SAFE>(img, x, y0 + 1, r3, okm2, okm1, okp1, okp2); sort5(r3);

    #pragma unroll
    for (int p = 0; p < PY; p += 2) {
        const int y = y0 + p;
        load_row<SAFE>(img, x, y + 2, r4, okm2, okm1, okp1, okp2); sort5(r4);
        load_row<SAFE>(img, x, y + 3, r5, okm2, okm1, okp1, okp2); sort5(r5);

        // Shared per-column sort4 of the 4 common rows — ON THE FMA PIPE
        // (125 fma ops/pair, overlapping the alu-pipe comparator stream).
        float q[5][4];
        #pragma unroll
        for (int j = 0; j < 5; ++j) {
            sort4f(r1[j], r2[j], r3[j], r4[j],
                   q[j][0], q[j][1], q[j][2], q[j][3]);
        }

        // Shared: sort the 8 shared candidates (3 presorted pairs + 1 pair),
        // Batcher merge; drop global min & max -> sorted middle-6 sA..sF. (alu)
        float A0 = q[2][1], A1 = q[2][2];
        float B0 = q[3][0], B1 = q[3][1];
        float C0 = q[1][2], C1 = q[1][3];
        float D0 = q[0][3], D1 = q[4][0];
        s2(D0, D1);
        s2(A0, B0); s2(A1, B1); s2(A1, B0);   // X = (A0,A1,B0,B1) sorted
        s2(C0, D0); s2(C1, D1); s2(C1, D0);   // Y = (C0,C1,D0,D1) sorted
        s2(A0, C0); s2(B0, D0); s2(B0, C0);   // even-merge
        s2(A1, C1); s2(B1, D1); s2(B1, C1);   // odd-merge
        s2(A1, B0); s2(B1, C0); s2(C1, D0);   // fixup
        const float sA = A1, sB = B0, sC = B1, sD = C0, sE = C1, sF = D0;

        // Per pixel: merge private row, then sorted-buffer forgetful chain. (alu)
        #pragma unroll
        for (int pix = 0; pix < 2; ++pix) {
            const float* rp = pix ? r5 : r0;
            const float a0 = rp[0], a1 = rp[1], a2 = rp[2], a3 = rp[3], a4 = rp[4];

            const float t0b = fmaxf(q[0][2], a0);                   // col0 private
            const float t1c = fmaxf(q[1][1], a1);                   // col1 private
            const float t2c = fminf(fmaxf(a2, q[2][0]), q[2][3]);   // col2 clamp
            const float t3c = fminf(q[3][2], a3);                   // col3 private
            const float t4b = fminf(q[4][1], a4);                   // col4 private

            // sorted6 + t0b -> middles = sorted4 + 1 floater.
            const float f1 = fminf(fmaxf(t0b, sA), sF);
            // {sB..sE} + {f1, t1c} -> middles = (sC,sD) + 2 floaters.
            float lo = f1, hi = t1c; s2(lo, hi);
            const float g1 = fmaxf(sB, lo);
            const float g2 = fminf(sE, hi);
            // {sC,sD} + {g1,g2,t2c} -> sort3 floaters, clamp ends.
            float u0 = g1, u1 = g2, u2 = t2c;
            s2(u0, u1); s2(u1, u2); s2(u0, u1);
            const float w0 = fmaxf(sC, u0);
            const float w2 = fminf(sD, u2);
            // {w0,u1,w2} + t3c -> minmax4 middles.
            float m0 = w0, m1 = u1, m2 = w2, m3 = t3c;
            s2(m0, m1); s2(m2, m3); s2(m0, m2); s2(m1, m3);
            outp[(y + pix) * IMW] = med3f(m1, m2, t4b);
        }

        // Slide window down two rows (renamed away under full unroll).
        #pragma unroll
        for (int j = 0; j < 5; ++j) {
            r0[j] = r2[j]; r1[j] = r3[j]; r2[j] = r4[j]; r3[j] = r5[j];
        }
    }
}

__global__ void __launch_bounds__(128)
median5x5_kernel(const float* __restrict__ in, float* __restrict__ out) {
    const int x  = blockIdx.x * 32 + threadIdx.x;
    const int y0 = (blockIdx.y * YB + threadIdx.y) * PY;
    const long imgoff = (long)blockIdx.z << 20;  // 1024*1024 per image
    const float* img = in + imgoff;
    float* outp = out + imgoff + x;

    // Block-uniform branch: interior blocks (88%) take the check-free path.
    const bool safe = (blockIdx.x != 0) & (blockIdx.x != gridDim.x - 1) &
                      (blockIdx.y != 0) & (blockIdx.y != gridDim.y - 1);
    if (safe) {
        process_strip<true >(img, outp, x, y0);
    } else {
        process_strip<false>(img, outp, x, y0);
    }
}

}  // namespace

extern "C" void kernel_launch(void* const* d_in, const int* in_sizes, int n_in,
                              void* d_out, int out_size) {
    const float* x = (const float*)d_in[0];
    float* out = (float*)d_out;
    const int nimg = out_size / (IMW * IMH);   // B*C = 8
    dim3 block(32, YB, 1);
    dim3 grid(IMW / 32, IMH / (YB * PY), nimg);   // (32, 32, 8) = 8192 blocks
    median5x5_kernel<<<grid, block>>>(x, out);
}

// round 12
// speedup vs baseline: 1.0491x; 1.0491x over previous
#include <cuda_runtime.h>
#include <cuda_bf16.h>

namespace {

constexpr int IMW = 1024;
constexpr int IMH = 1024;
constexpr int PY  = 8;        // output rows per thread (processed in vertical pairs)
constexpr int YB  = 4;        // blockDim.y

__device__ __forceinline__ void s2(float &a, float &b) {
    float t = fminf(a, b);
    b = fmaxf(a, b);
    a = t;
}

// 9-comparator sort5 (Batcher sort4 + insertion chain).
__device__ __forceinline__ void sort5(float v[5]) {
    s2(v[0], v[1]); s2(v[2], v[3]); s2(v[0], v[2]); s2(v[1], v[3]); s2(v[1], v[2]);
    s2(v[3], v[4]); s2(v[2], v[3]); s2(v[1], v[2]); s2(v[0], v[1]);
}

// 5-comparator sort4.
__device__ __forceinline__ void sort4(float &a, float &b, float &c, float &d) {
    s2(a, b); s2(c, d); s2(a, c); s2(b, d); s2(b, c);
}

__device__ __forceinline__ float med3f(float a, float b, float c) {
    return fmaxf(fminf(a, b), fminf(fmaxf(a, b), c));
}

template <bool SAFE>
__device__ __forceinline__ void load_row(const float* __restrict__ img, int x, int yy,
                                         float v[5],
                                         bool okm2, bool okm1, bool okp1, bool okp2) {
    if (SAFE || (unsigned)yy < (unsigned)IMH) {
        const float* p = img + yy * IMW + x;
        v[0] = (SAFE || okm2) ? __ldg(p - 2) : 0.0f;
        v[1] = (SAFE || okm1) ? __ldg(p - 1) : 0.0f;
        v[2] = __ldg(p);
        v[3] = (SAFE || okp1) ? __ldg(p + 1) : 0.0f;
        v[4] = (SAFE || okp2) ? __ldg(p + 2) : 0.0f;
    } else {
        v[0] = v[1] = v[2] = v[3] = v[4] = 0.0f;
    }
}

template <bool SAFE>
__device__ __forceinline__ void process_strip(const float* __restrict__ img,
                                              float* __restrict__ outp,
                                              int x, int y0) {
    const bool okm2 = SAFE || (x >= 2);
    const bool okm1 = SAFE || (x >= 1);
    const bool okp1 = SAFE || (x <= IMW - 2);
    const bool okp2 = SAFE || (x <= IMW - 3);

    // Sorted horizontal 5-windows. For the pair (y, y+1):
    // r0 = y-2 (private to pixel A), r1..r4 = y-1..y+2 (common), r5 = y+3 (private B).
    float r0[5], r1[5], r2[5], r3[5], r4[5], r5[5];
    load_row<SAFE>(img, x, y0 - 2, r0, okm2, okm1, okp1, okp2); sort5(r0);
    load_row<SAFE>(img, x, y0 - 1, r1, okm2, okm1, okp1, okp2); sort5(r1);
    load_row<SAFE>(img, x, y0 + 0, r2, okm2, okm1, okp1, okp2); sort5(r2);
    load_row<SAFE>(img, x, y0 + 1, r3, okm2, okm1, okp1, okp2); sort5(r3);

    #pragma unroll
    for (int p = 0; p < PY; p += 2) {
        const int y = y0 + p;
        load_row<SAFE>(img, x, y + 2, r4, okm2, okm1, okp1, okp2); sort5(r4);
        load_row<SAFE>(img, x, y + 3, r5, okm2, okm1, okp1, okp2); sort5(r5);

        // Shared per-column sort4 of the 4 common rows (doubly sorted q).
        float q[5][4];
        #pragma unroll
        for (int j = 0; j < 5; ++j) {
            q[j][0] = r1[j]; q[j][1] = r2[j]; q[j][2] = r3[j]; q[j][3] = r4[j];
            sort4(q[j][0], q[j][1], q[j][2], q[j][3]);
        }

        // Shared: sort the 8 shared candidates (3 presorted pairs + 1 pair),
        // Batcher merge; drop global min & max -> sorted middle-6 sA..sF.
        float A0 = q[2][1], A1 = q[2][2];
        float B0 = q[3][0], B1 = q[3][1];
        float C0 = q[1][2], C1 = q[1][3];
        float D0 = q[0][3], D1 = q[4][0];
        s2(D0, D1);
        s2(A0, B0); s2(A1, B1); s2(A1, B0);   // X = (A0,A1,B0,B1) sorted
        s2(C0, D0); s2(C1, D1); s2(C1, D0);   // Y = (C0,C1,D0,D1) sorted
        s2(A0, C0); s2(B0, D0); s2(B0, C0);   // even-merge
        s2(A1, C1); s2(B1, D1); s2(B1, C1);   // odd-merge
        s2(A1, B0); s2(B1, C0); s2(C1, D0);   // fixup
        const float sA = A1, sB = B0, sC = B1, sD = C0, sE = C1, sF = D0;

        // Per pixel: merge private row, then sorted-buffer forgetful chain.
        #pragma unroll
        for (int pix = 0; pix < 2; ++pix) {
            const float* rp = pix ? r5 : r0;
            const float a0 = rp[0], a1 = rp[1], a2 = rp[2], a3 = rp[3], a4 = rp[4];

            const float t0b = fmaxf(q[0][2], a0);                   // col0 private
            const float t1c = fmaxf(q[1][1], a1);                   // col1 private
            const float t2c = fminf(fmaxf(a2, q[2][0]), q[2][3]);   // col2 clamp
            const float t3c = fminf(q[3][2], a3);                   // col3 private
            const float t4b = fminf(q[4][1], a4);                   // col4 private

            // sorted6 + t0b -> middles = sorted4 + 1 floater.
            const float f1 = fminf(fmaxf(t0b, sA), sF);
            // {sB..sE} + {f1, t1c} -> middles = (sC,sD) + 2 floaters.
            float lo = f1, hi = t1c; s2(lo, hi);
            const float g1 = fmaxf(sB, lo);
            const float g2 = fminf(sE, hi);
            // {sC,sD} + {g1,g2,t2c} -> sort3 floaters, clamp ends.
            float u0 = g1, u1 = g2, u2 = t2c;
            s2(u0, u1); s2(u1, u2); s2(u0, u1);
            const float w0 = fmaxf(sC, u0);
            const float w2 = fminf(sD, u2);
            // {w0,u1,w2} + t3c -> minmax4 middles.
            float m0 = w0, m1 = u1, m2 = w2, m3 = t3c;
            s2(m0, m1); s2(m2, m3); s2(m0, m2); s2(m1, m3);
            outp[(y + pix) * IMW] = med3f(m1, m2, t4b);
        }

        // Slide window down two rows (renamed away under full unroll).
        #pragma unroll
        for (int j = 0; j < 5; ++j) {
            r0[j] = r2[j]; r1[j] = r3[j]; r2[j] = r4[j]; r3[j] = r5[j];
        }
    }
}

// minBlocksPerMP=10 -> ptxas targets <=51 regs -> 10 CTAs/SM = 40 warps
// (62.5% occupancy cap vs the previous 32-warp/50% register cap).
__global__ void __launch_bounds__(128, 10)
median5x5_kernel(const float* __restrict__ in, float* __restrict__ out) {
    const int x  = blockIdx.x * 32 + threadIdx.x;
    const int y0 = (blockIdx.y * YB + threadIdx.y) * PY;
    const long imgoff = (long)blockIdx.z << 20;  // 1024*1024 per image
    const float* img = in + imgoff;
    float* outp = out + imgoff + x;

    // Block-uniform branch: interior blocks (88%) take the check-free path.
    const bool safe = (blockIdx.x != 0) & (blockIdx.x != gridDim.x - 1) &
                      (blockIdx.y != 0) & (blockIdx.y != gridDim.y - 1);
    if (safe) {
        process_strip<true >(img, outp, x, y0);
    } else {
        process_strip<false>(img, outp, x, y0);
    }
}

}  // namespace

extern "C" void kernel_launch(void* const* d_in, const int* in_sizes, int n_in,
                              void* d_out, int out_size) {
    const float* x = (const float*)d_in[0];
    float* out = (float*)d_out;
    const int nimg = out_size / (IMW * IMH);   // B*C = 8
    dim3 block(32, YB, 1);
    dim3 grid(IMW / 32, IMH / (YB * PY), nimg);   // (32, 32, 8) = 8192 blocks
    median5x5_kernel<<<grid, block>>>(x, out);
}